// round 6
// baseline (speedup 1.0000x reference)
#include <cuda_runtime.h>
#include <math.h>

// ---------------------------------------------------------------------------
// PositionEvaluator, round 5 (re-run of the NT=512 variant; round-5 infra
// failure was container acquisition, not a kernel verdict).
// One CTA processes R=16 focal rows; each thread handles a ROW PAIR packed
// into 64-bit f32x2 lanes (fma.rn.f32x2). 16 warps/CTA (4 per SMSP) to cover
// LDS/FMA latency. Thread map: p = tid & 7 (row pair), g = tid >> 3 (group).
// ---------------------------------------------------------------------------

#define R  16          // rows per CTA
#define G  64          // channel groups
#define NT 512

typedef unsigned long long u64;
union F2 { u64 u; float2 f; };

__device__ __forceinline__ u64 ffma2(u64 a, u64 b, u64 c) {
  u64 d; asm("fma.rn.f32x2 %0, %1, %2, %3;" : "=l"(d) : "l"(a), "l"(b), "l"(c)); return d;
}
__device__ __forceinline__ u64 fmul2(u64 a, u64 b) {
  u64 d; asm("mul.rn.f32x2 %0, %1, %2;" : "=l"(d) : "l"(a), "l"(b)); return d;
}
__device__ __forceinline__ u64 dup2(float w) {
  u64 d; asm("mov.b64 %0, {%1, %1};" : "=l"(d) : "f"(w)); return d;
}
__device__ __forceinline__ u64 ld2(const float* p) {
  return *reinterpret_cast<const u64*>(p);
}
__device__ __forceinline__ void st2(float* p, u64 v) {
  *reinterpret_cast<u64*>(p) = v;
}

struct SM {
  float sv[3][256][R];    // current vector activations (comp, channel, row)
  float sh[3][256][R];    // vh / d scratch
  float snorm[256][R];    // ||vh|| per channel
  float ssc[256][R];      // scalar activations
  float so[128][R];       // out_s / final reduce scratch
  float rp[3][R];         // relpos
  int   nidx[R];
};

// y[i][o][pair] = sum_c W[o][c] * x[i][c][pair];  optionally nrm = ||y||
template<int OUT, int CIN, bool NORM>
__device__ __forceinline__ void matvec_v(const float* __restrict__ W,
                                         float (*x)[256][R],
                                         float (*y)[256][R],
                                         float (*nrm)[R],
                                         int g, int p)
{
  constexpr int J = OUT / G;
  u64 acc[J][3];
#pragma unroll
  for (int j = 0; j < J; ++j) { acc[j][0] = 0ull; acc[j][1] = 0ull; acc[j][2] = 0ull; }
#pragma unroll 1
  for (int c = 0; c < CIN; c += 4) {
    u64 xv[3][4];
#pragma unroll
    for (int cc = 0; cc < 4; ++cc) {
      xv[0][cc] = ld2(&x[0][c + cc][2 * p]);
      xv[1][cc] = ld2(&x[1][c + cc][2 * p]);
      xv[2][cc] = ld2(&x[2][c + cc][2 * p]);
    }
#pragma unroll
    for (int j = 0; j < J; ++j) {
      const int o = g + G * j;
      const float4 w = __ldg(reinterpret_cast<const float4*>(W + (size_t)o * CIN + c));
      const u64 w0 = dup2(w.x), w1 = dup2(w.y), w2 = dup2(w.z), w3 = dup2(w.w);
#pragma unroll
      for (int i = 0; i < 3; ++i) {
        acc[j][i] = ffma2(w0, xv[i][0], acc[j][i]);
        acc[j][i] = ffma2(w1, xv[i][1], acc[j][i]);
        acc[j][i] = ffma2(w2, xv[i][2], acc[j][i]);
        acc[j][i] = ffma2(w3, xv[i][3], acc[j][i]);
      }
    }
  }
#pragma unroll
  for (int j = 0; j < J; ++j) {
    const int o = g + G * j;
    st2(&y[0][o][2 * p], acc[j][0]);
    st2(&y[1][o][2 * p], acc[j][1]);
    st2(&y[2][o][2 * p], acc[j][2]);
    if (NORM) {
      u64 s = fmul2(acc[j][0], acc[j][0]);
      s = ffma2(acc[j][1], acc[j][1], s);
      s = ffma2(acc[j][2], acc[j][2], s);
      F2 t; t.u = s;
      F2 n; n.f.x = sqrtf(t.f.x); n.f.y = sqrtf(t.f.y);
      st2(&nrm[o][2 * p], n.u);
    }
  }
}

// y[o][pair] = sum_{k<K1} W[o][k]*x1[k][pair] + sum_{k<K2} W[o][K1+k]*x2[k][pair]
template<int OUT, int K1, int K2>
__device__ __forceinline__ void matvec_s2(const float* __restrict__ W,
                                          float (*x1)[R], float (*x2)[R],
                                          float (*y)[R], int g, int p)
{
  constexpr int J = OUT / G;
  constexpr int K = K1 + K2;
  u64 acc[J];
#pragma unroll
  for (int j = 0; j < J; ++j) acc[j] = 0ull;
#pragma unroll 1
  for (int k = 0; k < K1; k += 4) {
    u64 xv[4];
#pragma unroll
    for (int kk = 0; kk < 4; ++kk) xv[kk] = ld2(&x1[k + kk][2 * p]);
#pragma unroll
    for (int j = 0; j < J; ++j) {
      const int o = g + G * j;
      const float4 w = __ldg(reinterpret_cast<const float4*>(W + (size_t)o * K + k));
      acc[j] = ffma2(dup2(w.x), xv[0], acc[j]);
      acc[j] = ffma2(dup2(w.y), xv[1], acc[j]);
      acc[j] = ffma2(dup2(w.z), xv[2], acc[j]);
      acc[j] = ffma2(dup2(w.w), xv[3], acc[j]);
    }
  }
#pragma unroll 1
  for (int k = 0; k < K2; k += 4) {
    u64 xv[4];
#pragma unroll
    for (int kk = 0; kk < 4; ++kk) xv[kk] = ld2(&x2[k + kk][2 * p]);
#pragma unroll
    for (int j = 0; j < J; ++j) {
      const int o = g + G * j;
      const float4 w = __ldg(reinterpret_cast<const float4*>(W + (size_t)o * K + K1 + k));
      acc[j] = ffma2(dup2(w.x), xv[0], acc[j]);
      acc[j] = ffma2(dup2(w.y), xv[1], acc[j]);
      acc[j] = ffma2(dup2(w.z), xv[2], acc[j]);
      acc[j] = ffma2(dup2(w.w), xv[3], acc[j]);
    }
  }
#pragma unroll
  for (int j = 0; j < J; ++j) st2(&y[g + G * j][2 * p], acc[j]);
}

// v[i][o][pair] = sigmoid(Wg[o]·so + bg[o]) * sum_h Wvo[o][h] * vh[i][h][pair]
template<int OUT, int H, int KG>
__device__ __forceinline__ void gated_outv(const float* __restrict__ Wvo,
                                           const float* __restrict__ Wg,
                                           const float* __restrict__ bg,
                                           float (*vh)[256][R],
                                           float (*so)[R],
                                           float (*v)[256][R],
                                           int g, int p)
{
  constexpr int J = OUT / G;
  u64 gacc[J];
#pragma unroll
  for (int j = 0; j < J; ++j) gacc[j] = 0ull;
#pragma unroll 1
  for (int k = 0; k < KG; k += 4) {
    u64 xv[4];
#pragma unroll
    for (int kk = 0; kk < 4; ++kk) xv[kk] = ld2(&so[k + kk][2 * p]);
#pragma unroll
    for (int j = 0; j < J; ++j) {
      const int o = g + G * j;
      const float4 w = __ldg(reinterpret_cast<const float4*>(Wg + (size_t)o * KG + k));
      gacc[j] = ffma2(dup2(w.x), xv[0], gacc[j]);
      gacc[j] = ffma2(dup2(w.y), xv[1], gacc[j]);
      gacc[j] = ffma2(dup2(w.z), xv[2], gacc[j]);
      gacc[j] = ffma2(dup2(w.w), xv[3], gacc[j]);
    }
  }
  u64 gate[J];
#pragma unroll
  for (int j = 0; j < J; ++j) {
    const float b = __ldg(&bg[g + G * j]);
    F2 t; t.u = gacc[j];
    F2 gt;
    gt.f.x = 1.f / (1.f + __expf(-(t.f.x + b)));
    gt.f.y = 1.f / (1.f + __expf(-(t.f.y + b)));
    gate[j] = gt.u;
  }
  u64 acc[J][3];
#pragma unroll
  for (int j = 0; j < J; ++j) { acc[j][0] = 0ull; acc[j][1] = 0ull; acc[j][2] = 0ull; }
#pragma unroll 1
  for (int h = 0; h < H; h += 4) {
    u64 xv[3][4];
#pragma unroll
    for (int cc = 0; cc < 4; ++cc) {
      xv[0][cc] = ld2(&vh[0][h + cc][2 * p]);
      xv[1][cc] = ld2(&vh[1][h + cc][2 * p]);
      xv[2][cc] = ld2(&vh[2][h + cc][2 * p]);
    }
#pragma unroll
    for (int j = 0; j < J; ++j) {
      const int o = g + G * j;
      const float4 w = __ldg(reinterpret_cast<const float4*>(Wvo + (size_t)o * H + h));
      const u64 w0 = dup2(w.x), w1 = dup2(w.y), w2 = dup2(w.z), w3 = dup2(w.w);
#pragma unroll
      for (int i = 0; i < 3; ++i) {
        acc[j][i] = ffma2(w0, xv[i][0], acc[j][i]);
        acc[j][i] = ffma2(w1, xv[i][1], acc[j][i]);
        acc[j][i] = ffma2(w2, xv[i][2], acc[j][i]);
        acc[j][i] = ffma2(w3, xv[i][3], acc[j][i]);
      }
    }
  }
#pragma unroll
  for (int j = 0; j < J; ++j) {
    const int o = g + G * j;
    st2(&v[0][o][2 * p], fmul2(gate[j], acc[j][0]));
    st2(&v[1][o][2 * p], fmul2(gate[j], acc[j][1]));
    st2(&v[2][o][2 * p], fmul2(gate[j], acc[j][2]));
  }
}

template<int OUT, bool LEAKY>
__device__ __forceinline__ void scalar_act(float (*so)[R], float (*dst)[R], int g, int p)
{
  constexpr int J = OUT / G;
#pragma unroll
  for (int j = 0; j < J; ++j) {
    const int o = g + G * j;
    F2 t; t.u = ld2(&so[o][2 * p]);
    if (LEAKY) {
      t.f.x = t.f.x >= 0.f ? t.f.x : 0.01f * t.f.x;
      t.f.y = t.f.y >= 0.f ? t.f.y : 0.01f * t.f.y;
    }
    st2(&dst[o][2 * p], t.u);
  }
}

template<int OUT>
__device__ __forceinline__ void vnleaky_ew(float (*x)[256][R], float (*d)[256][R], int g, int p)
{
  constexpr int J = OUT / G;
#pragma unroll
  for (int j = 0; j < J; ++j) {
    const int o = g + G * j;
    F2 x0, x1, x2, d0, d1, d2;
    x0.u = ld2(&x[0][o][2 * p]); x1.u = ld2(&x[1][o][2 * p]); x2.u = ld2(&x[2][o][2 * p]);
    d0.u = ld2(&d[0][o][2 * p]); d1.u = ld2(&d[1][o][2 * p]); d2.u = ld2(&d[2][o][2 * p]);
    u64 dotu = fmul2(x0.u, d0.u); dotu = ffma2(x1.u, d1.u, dotu); dotu = ffma2(x2.u, d2.u, dotu);
    u64 dsqu = fmul2(d0.u, d0.u); dsqu = ffma2(d1.u, d1.u, dsqu); dsqu = ffma2(d2.u, d2.u, dsqu);
    F2 dot, dsq; dot.u = dotu; dsq.u = dsqu;
    F2 o0, o1, o2;
#pragma unroll
    for (int h = 0; h < 2; ++h) {
      const float dt = h ? dot.f.y : dot.f.x;
      const float ds = h ? dsq.f.y : dsq.f.x;
      const float xa = h ? x0.f.y : x0.f.x;
      const float xb = h ? x1.f.y : x1.f.x;
      const float xc = h ? x2.f.y : x2.f.x;
      const float da = h ? d0.f.y : d0.f.x;
      const float db = h ? d1.f.y : d1.f.x;
      const float dc = h ? d2.f.y : d2.f.x;
      const float t = dt / (ds + 1e-6f);
      const bool pos = (dt >= 0.f);
      const float na = pos ? xa : (xa - t * da);
      const float nb = pos ? xb : (xb - t * db);
      const float nc = pos ? xc : (xc - t * dc);
      const float ra = 0.2f * xa + 0.8f * na;
      const float rb = 0.2f * xb + 0.8f * nb;
      const float rc = 0.2f * xc + 0.8f * nc;
      if (h) { o0.f.y = ra; o1.f.y = rb; o2.f.y = rc; }
      else   { o0.f.x = ra; o1.f.x = rb; o2.f.x = rc; }
    }
    st2(&x[0][o][2 * p], o0.u);
    st2(&x[1][o][2 * p], o1.u);
    st2(&x[2][o][2 * p], o2.u);
  }
}

__global__ __launch_bounds__(NT, 1)
void pe_kernel(const float* __restrict__ h_sca, const float* __restrict__ h_vec,
               const float* __restrict__ pos_compose, const float* __restrict__ pos,
               const float* __restrict__ g1_Wvh, const float* __restrict__ g1_Ws,
               const float* __restrict__ g1_Wvo, const float* __restrict__ g1_Wg,
               const float* __restrict__ g1_bg,  const float* __restrict__ g1_Wd,
               const float* __restrict__ g2_Wvh, const float* __restrict__ g2_Ws,
               const float* __restrict__ g2_Wvo, const float* __restrict__ g2_Wg,
               const float* __restrict__ g2_bg,
               const float* __restrict__ a1_Wvh, const float* __restrict__ a1_Ws,
               const float* __restrict__ a1_Wvo, const float* __restrict__ a1_Wg,
               const float* __restrict__ a1_bg,  const float* __restrict__ a1_Wd,
               const float* __restrict__ a2_Wvh, const float* __restrict__ a2_Ws,
               const float* __restrict__ a2_Wvo, const float* __restrict__ a2_Wg,
               const float* __restrict__ a2_bg,  const float* __restrict__ a2_Wd,
               const float* __restrict__ f_Wvh,  const float* __restrict__ f_Ws,
               const int* __restrict__ idx_focal,
               float* __restrict__ out, int F)
{
  extern __shared__ char smraw[];
  SM& S = *reinterpret_cast<SM*>(smraw);
  const int tid = threadIdx.x;
  const int g = tid >> 3;    // channel group 0..63
  const int p = tid & 7;     // row pair     0..7
  const int row0 = blockIdx.x * R;

  if (tid < R) {
    const int row = row0 + tid;
    S.nidx[tid] = (row < F) ? idx_focal[row] : 0;
  }
  __syncthreads();

  if (tid < 3 * R) {
    const int rr = tid / 3, i = tid % 3;
    const int row = row0 + rr;
    const int n = S.nidx[rr];
    const float pv = (row < F) ? pos[(size_t)row * 3 + i] : 0.f;
    S.rp[i][rr] = pv - pos_compose[(size_t)n * 3 + i];
  }

  // gather: threads [0,256) do h_sca, threads [256,448) do h_vec
  if (tid < 256) {
    for (int rr = 0; rr < R; ++rr) {
      const size_t n = (size_t)S.nidx[rr];
      S.ssc[tid][rr] = __ldg(&h_sca[n * 256 + tid]);
    }
  } else if (tid < 256 + 192) {
    const int t2 = tid - 256;
    for (int rr = 0; rr < R; ++rr) {
      const size_t n = (size_t)S.nidx[rr];
      S.sv[t2 % 3][t2 / 3][rr] = __ldg(&h_vec[n * 192 + t2]);
    }
  }
  __syncthreads();

  // ================= g1: gv_perceptron =================
  matvec_v<128, 64, true>(g1_Wvh, S.sv, S.sh, S.snorm, g, p);
  __syncthreads();
  matvec_s2<128, 128, 256>(g1_Ws, S.snorm, S.ssc, S.so, g, p);
  __syncthreads();
  gated_outv<128, 128, 128>(g1_Wvo, g1_Wg, g1_bg, S.sh, S.so, S.sv, g, p);
  scalar_act<128, true>(S.so, S.ssc, g, p);
  __syncthreads();
  matvec_v<128, 128, false>(g1_Wd, S.sv, S.sh, S.snorm, g, p);
  __syncthreads();
  vnleaky_ew<128>(S.sv, S.sh, g, p);
  __syncthreads();

  // ================= g2: gv_linear =================
  matvec_v<128, 128, true>(g2_Wvh, S.sv, S.sh, S.snorm, g, p);
  __syncthreads();
  matvec_s2<128, 128, 128>(g2_Ws, S.snorm, S.ssc, S.so, g, p);
  __syncthreads();
  gated_outv<128, 128, 128>(g2_Wvo, g2_Wg, g2_bg, S.sh, S.so, S.sv, g, p);
  scalar_act<128, false>(S.so, S.ssc, g, p);
  __syncthreads();

  // ================= a1: gv_perceptron =================
  matvec_v<256, 128, true>(a1_Wvh, S.sv, S.sh, S.snorm, g, p);
  __syncthreads();
  matvec_s2<128, 256, 128>(a1_Ws, S.snorm, S.ssc, S.so, g, p);
  __syncthreads();
  gated_outv<256, 256, 128>(a1_Wvo, a1_Wg, a1_bg, S.sh, S.so, S.sv, g, p);
  scalar_act<128, true>(S.so, S.ssc, g, p);
  __syncthreads();
  matvec_v<256, 256, false>(a1_Wd, S.sv, S.sh, S.snorm, g, p);
  __syncthreads();
  vnleaky_ew<256>(S.sv, S.sh, g, p);
  __syncthreads();

  // ===== split: inner = <x_vec2, relpos> -> ssc[128..255] =====
  {
    const u64 rp0 = ld2(&S.rp[0][2 * p]);
    const u64 rp1 = ld2(&S.rp[1][2 * p]);
    const u64 rp2 = ld2(&S.rp[2][2 * p]);
#pragma unroll
    for (int j = 0; j < 2; ++j) {
      const int o = g + G * j;
      u64 acc = fmul2(ld2(&S.sv[0][128 + o][2 * p]), rp0);
      acc = ffma2(ld2(&S.sv[1][128 + o][2 * p]), rp1, acc);
      acc = ffma2(ld2(&S.sv[2][128 + o][2 * p]), rp2, acc);
      st2(&S.ssc[128 + o][2 * p], acc);
    }
  }
  __syncthreads();

  // ================= a2: gv_perceptron (on x_vec = sv[0..127]) =================
  matvec_v<128, 128, true>(a2_Wvh, S.sv, S.sh, S.snorm, g, p);
  __syncthreads();
  matvec_s2<128, 128, 256>(a2_Ws, S.snorm, S.ssc, S.so, g, p);
  __syncthreads();
  gated_outv<128, 128, 128>(a2_Wvo, a2_Wg, a2_bg, S.sh, S.so, S.sv, g, p);
  scalar_act<128, true>(S.so, S.ssc, g, p);
  __syncthreads();
  matvec_v<128, 128, false>(a2_Wd, S.sv, S.sh, S.snorm, g, p);
  __syncthreads();
  vnleaky_ew<128>(S.sv, S.sh, g, p);
  __syncthreads();

  // ================= final: out = [||f_Wvh@v||, s3] @ f_Ws^T =================
  matvec_v<128, 128, true>(f_Wvh, S.sv, S.sh, S.snorm, g, p);
  __syncthreads();
  {
    u64 acc = 0ull;
#pragma unroll
    for (int kk = 0; kk < 4; ++kk) {
      const int k = g * 4 + kk;
      const u64 xv = (k < 128) ? ld2(&S.snorm[k][2 * p]) : ld2(&S.ssc[k - 128][2 * p]);
      acc = ffma2(dup2(__ldg(&f_Ws[k])), xv, acc);
    }
    st2(&S.so[g][2 * p], acc);
  }
  __syncthreads();
  if (tid < R) {
    const int row = row0 + tid;
    float acc = 0.f;
#pragma unroll
    for (int gg = 0; gg < G; ++gg) acc += S.so[gg][tid];
    if (row < F) out[row] = acc;
  }
}

extern "C" void kernel_launch(void* const* d_in, const int* in_sizes, int n_in,
                              void* d_out, int out_size)
{
  const float* h_sca       = (const float*)d_in[0];
  const float* h_vec       = (const float*)d_in[1];
  const float* pos_compose = (const float*)d_in[2];
  const float* pos         = (const float*)d_in[3];
  const float* g1_Wvh = (const float*)d_in[4];
  const float* g1_Ws  = (const float*)d_in[5];
  const float* g1_Wvo = (const float*)d_in[6];
  const float* g1_Wg  = (const float*)d_in[7];
  const float* g1_bg  = (const float*)d_in[8];
  const float* g1_Wd  = (const float*)d_in[9];
  const float* g2_Wvh = (const float*)d_in[10];
  const float* g2_Ws  = (const float*)d_in[11];
  const float* g2_Wvo = (const float*)d_in[12];
  const float* g2_Wg  = (const float*)d_in[13];
  const float* g2_bg  = (const float*)d_in[14];
  const float* a1_Wvh = (const float*)d_in[15];
  const float* a1_Ws  = (const float*)d_in[16];
  const float* a1_Wvo = (const float*)d_in[17];
  const float* a1_Wg  = (const float*)d_in[18];
  const float* a1_bg  = (const float*)d_in[19];
  const float* a1_Wd  = (const float*)d_in[20];
  const float* a2_Wvh = (const float*)d_in[21];
  const float* a2_Ws  = (const float*)d_in[22];
  const float* a2_Wvo = (const float*)d_in[23];
  const float* a2_Wg  = (const float*)d_in[24];
  const float* a2_bg  = (const float*)d_in[25];
  const float* a2_Wd  = (const float*)d_in[26];
  const float* f_Wvh  = (const float*)d_in[27];
  const float* f_Ws   = (const float*)d_in[28];
  const int*   idx_focal = (const int*)d_in[29];

  const int F = in_sizes[3] / 3;   // pos is (F, 3)
  const int grid = (F + R - 1) / R;

  cudaFuncSetAttribute(pe_kernel, cudaFuncAttributeMaxDynamicSharedMemorySize,
                       (int)sizeof(SM));

  pe_kernel<<<grid, NT, sizeof(SM)>>>(
      h_sca, h_vec, pos_compose, pos,
      g1_Wvh, g1_Ws, g1_Wvo, g1_Wg, g1_bg, g1_Wd,
      g2_Wvh, g2_Ws, g2_Wvo, g2_Wg, g2_bg,
      a1_Wvh, a1_Ws, a1_Wvo, a1_Wg, a1_bg, a1_Wd,
      a2_Wvh, a2_Ws, a2_Wvo, a2_Wg, a2_bg, a2_Wd,
      f_Wvh, f_Ws, idx_focal,
      (float*)d_out, F);
}

// round 9
// speedup vs baseline: 1.0651x; 1.0651x over previous
#include <cuda_runtime.h>
#include <math.h>

// ---------------------------------------------------------------------------
// PositionEvaluator, round 8: back to the ONLY launch config that has ever
// benched (NT=256, R=16, occ=1), with unroll-by-8 inner loops (two static
// xv buffers) so the second half's LDS issue overlaps the first half's FMA
// chain -> loop-carried LDS stall paid once per 8 channels instead of per 4.
// Thread map: p = tid & 7 (row pair 0..7), g = tid >> 3 (channel group 0..31).
// ---------------------------------------------------------------------------

#define R  16          // rows per CTA
#define G  32          // channel groups
#define NT 256

typedef unsigned long long u64;
union F2 { u64 u; float2 f; };

__device__ __forceinline__ u64 ffma2(u64 a, u64 b, u64 c) {
  u64 d; asm("fma.rn.f32x2 %0, %1, %2, %3;" : "=l"(d) : "l"(a), "l"(b), "l"(c)); return d;
}
__device__ __forceinline__ u64 fmul2(u64 a, u64 b) {
  u64 d; asm("mul.rn.f32x2 %0, %1, %2;" : "=l"(d) : "l"(a), "l"(b)); return d;
}
__device__ __forceinline__ u64 dup2(float w) {
  u64 d; asm("mov.b64 %0, {%1, %1};" : "=l"(d) : "f"(w)); return d;
}
__device__ __forceinline__ u64 ld2(const float* p) {
  return *reinterpret_cast<const u64*>(p);
}
__device__ __forceinline__ void st2(float* p, u64 v) {
  *reinterpret_cast<u64*>(p) = v;
}

struct SM {
  float sv[3][256][R];    // current vector activations (comp, channel, row)
  float sh[3][256][R];    // vh / d scratch
  float snorm[256][R];    // ||vh|| per channel
  float ssc[256][R];      // scalar activations
  float so[128][R];       // out_s / final reduce scratch
  float rp[3][R];         // relpos
  int   nidx[R];
};

// y[i][o][pair] = sum_c W[o][c] * x[i][c][pair];  optionally nrm = ||y||
template<int OUT, int CIN, bool NORM>
__device__ __forceinline__ void matvec_v(const float* __restrict__ W,
                                         float (*x)[256][R],
                                         float (*y)[256][R],
                                         float (*nrm)[R],
                                         int g, int p)
{
  constexpr int J = OUT / G;
  u64 acc[J][3];
#pragma unroll
  for (int j = 0; j < J; ++j) { acc[j][0] = 0ull; acc[j][1] = 0ull; acc[j][2] = 0ull; }
#pragma unroll 1
  for (int c = 0; c < CIN; c += 8) {
    u64 xa[3][4], xb[3][4];
#pragma unroll
    for (int cc = 0; cc < 4; ++cc) {
      xa[0][cc] = ld2(&x[0][c + cc][2 * p]);
      xa[1][cc] = ld2(&x[1][c + cc][2 * p]);
      xa[2][cc] = ld2(&x[2][c + cc][2 * p]);
    }
#pragma unroll
    for (int cc = 0; cc < 4; ++cc) {
      xb[0][cc] = ld2(&x[0][c + 4 + cc][2 * p]);
      xb[1][cc] = ld2(&x[1][c + 4 + cc][2 * p]);
      xb[2][cc] = ld2(&x[2][c + 4 + cc][2 * p]);
    }
#pragma unroll
    for (int j = 0; j < J; ++j) {
      const int o = g + G * j;
      const float4 wa = __ldg(reinterpret_cast<const float4*>(W + (size_t)o * CIN + c));
      const float4 wb = __ldg(reinterpret_cast<const float4*>(W + (size_t)o * CIN + c + 4));
      const u64 a0 = dup2(wa.x), a1 = dup2(wa.y), a2 = dup2(wa.z), a3 = dup2(wa.w);
#pragma unroll
      for (int i = 0; i < 3; ++i) {
        acc[j][i] = ffma2(a0, xa[i][0], acc[j][i]);
        acc[j][i] = ffma2(a1, xa[i][1], acc[j][i]);
        acc[j][i] = ffma2(a2, xa[i][2], acc[j][i]);
        acc[j][i] = ffma2(a3, xa[i][3], acc[j][i]);
      }
      const u64 b0 = dup2(wb.x), b1 = dup2(wb.y), b2 = dup2(wb.z), b3 = dup2(wb.w);
#pragma unroll
      for (int i = 0; i < 3; ++i) {
        acc[j][i] = ffma2(b0, xb[i][0], acc[j][i]);
        acc[j][i] = ffma2(b1, xb[i][1], acc[j][i]);
        acc[j][i] = ffma2(b2, xb[i][2], acc[j][i]);
        acc[j][i] = ffma2(b3, xb[i][3], acc[j][i]);
      }
    }
  }
#pragma unroll
  for (int j = 0; j < J; ++j) {
    const int o = g + G * j;
    st2(&y[0][o][2 * p], acc[j][0]);
    st2(&y[1][o][2 * p], acc[j][1]);
    st2(&y[2][o][2 * p], acc[j][2]);
    if (NORM) {
      u64 s = fmul2(acc[j][0], acc[j][0]);
      s = ffma2(acc[j][1], acc[j][1], s);
      s = ffma2(acc[j][2], acc[j][2], s);
      F2 t; t.u = s;
      F2 n; n.f.x = sqrtf(t.f.x); n.f.y = sqrtf(t.f.y);
      st2(&nrm[o][2 * p], n.u);
    }
  }
}

// helper: accumulate an 8-wide scalar block from x into acc[J]
template<int J, int K>
__device__ __forceinline__ void sdot8(const float* __restrict__ W, int g, int base,
                                      float (*x)[R], u64 (&acc)[J], int p)
{
  u64 xa[4], xb[4];
#pragma unroll
  for (int kk = 0; kk < 4; ++kk) xa[kk] = ld2(&x[base % 0x7FFFFFFF + kk][2 * p]);
#pragma unroll
  for (int kk = 0; kk < 4; ++kk) xb[kk] = ld2(&x[base + 4 + kk][2 * p]);
#pragma unroll
  for (int j = 0; j < J; ++j) {
    (void)W; (void)K; (void)g;
  }
}

// y[o][pair] = sum_{k<K1} W[o][k]*x1[k][pair] + sum_{k<K2} W[o][K1+k]*x2[k][pair]
template<int OUT, int K1, int K2>
__device__ __forceinline__ void matvec_s2(const float* __restrict__ W,
                                          float (*x1)[R], float (*x2)[R],
                                          float (*y)[R], int g, int p)
{
  constexpr int J = OUT / G;
  constexpr int K = K1 + K2;
  u64 acc[J];
#pragma unroll
  for (int j = 0; j < J; ++j) acc[j] = 0ull;
#pragma unroll 1
  for (int k = 0; k < K1; k += 8) {
    u64 xa[4], xb[4];
#pragma unroll
    for (int kk = 0; kk < 4; ++kk) xa[kk] = ld2(&x1[k + kk][2 * p]);
#pragma unroll
    for (int kk = 0; kk < 4; ++kk) xb[kk] = ld2(&x1[k + 4 + kk][2 * p]);
#pragma unroll
    for (int j = 0; j < J; ++j) {
      const int o = g + G * j;
      const float4 wa = __ldg(reinterpret_cast<const float4*>(W + (size_t)o * K + k));
      const float4 wb = __ldg(reinterpret_cast<const float4*>(W + (size_t)o * K + k + 4));
      acc[j] = ffma2(dup2(wa.x), xa[0], acc[j]);
      acc[j] = ffma2(dup2(wa.y), xa[1], acc[j]);
      acc[j] = ffma2(dup2(wa.z), xa[2], acc[j]);
      acc[j] = ffma2(dup2(wa.w), xa[3], acc[j]);
      acc[j] = ffma2(dup2(wb.x), xb[0], acc[j]);
      acc[j] = ffma2(dup2(wb.y), xb[1], acc[j]);
      acc[j] = ffma2(dup2(wb.z), xb[2], acc[j]);
      acc[j] = ffma2(dup2(wb.w), xb[3], acc[j]);
    }
  }
#pragma unroll 1
  for (int k = 0; k < K2; k += 8) {
    u64 xa[4], xb[4];
#pragma unroll
    for (int kk = 0; kk < 4; ++kk) xa[kk] = ld2(&x2[k + kk][2 * p]);
#pragma unroll
    for (int kk = 0; kk < 4; ++kk) xb[kk] = ld2(&x2[k + 4 + kk][2 * p]);
#pragma unroll
    for (int j = 0; j < J; ++j) {
      const int o = g + G * j;
      const float4 wa = __ldg(reinterpret_cast<const float4*>(W + (size_t)o * K + K1 + k));
      const float4 wb = __ldg(reinterpret_cast<const float4*>(W + (size_t)o * K + K1 + k + 4));
      acc[j] = ffma2(dup2(wa.x), xa[0], acc[j]);
      acc[j] = ffma2(dup2(wa.y), xa[1], acc[j]);
      acc[j] = ffma2(dup2(wa.z), xa[2], acc[j]);
      acc[j] = ffma2(dup2(wa.w), xa[3], acc[j]);
      acc[j] = ffma2(dup2(wb.x), xb[0], acc[j]);
      acc[j] = ffma2(dup2(wb.y), xb[1], acc[j]);
      acc[j] = ffma2(dup2(wb.z), xb[2], acc[j]);
      acc[j] = ffma2(dup2(wb.w), xb[3], acc[j]);
    }
  }
#pragma unroll
  for (int j = 0; j < J; ++j) st2(&y[g + G * j][2 * p], acc[j]);
}

// v[i][o][pair] = sigmoid(Wg[o]·so + bg[o]) * sum_h Wvo[o][h] * vh[i][h][pair]
template<int OUT, int H, int KG>
__device__ __forceinline__ void gated_outv(const float* __restrict__ Wvo,
                                           const float* __restrict__ Wg,
                                           const float* __restrict__ bg,
                                           float (*vh)[256][R],
                                           float (*so)[R],
                                           float (*v)[256][R],
                                           int g, int p)
{
  constexpr int J = OUT / G;
  u64 gacc[J];
#pragma unroll
  for (int j = 0; j < J; ++j) gacc[j] = 0ull;
#pragma unroll 1
  for (int k = 0; k < KG; k += 8) {
    u64 xa[4], xb[4];
#pragma unroll
    for (int kk = 0; kk < 4; ++kk) xa[kk] = ld2(&so[k + kk][2 * p]);
#pragma unroll
    for (int kk = 0; kk < 4; ++kk) xb[kk] = ld2(&so[k + 4 + kk][2 * p]);
#pragma unroll
    for (int j = 0; j < J; ++j) {
      const int o = g + G * j;
      const float4 wa = __ldg(reinterpret_cast<const float4*>(Wg + (size_t)o * KG + k));
      const float4 wb = __ldg(reinterpret_cast<const float4*>(Wg + (size_t)o * KG + k + 4));
      gacc[j] = ffma2(dup2(wa.x), xa[0], gacc[j]);
      gacc[j] = ffma2(dup2(wa.y), xa[1], gacc[j]);
      gacc[j] = ffma2(dup2(wa.z), xa[2], gacc[j]);
      gacc[j] = ffma2(dup2(wa.w), xa[3], gacc[j]);
      gacc[j] = ffma2(dup2(wb.x), xb[0], gacc[j]);
      gacc[j] = ffma2(dup2(wb.y), xb[1], gacc[j]);
      gacc[j] = ffma2(dup2(wb.z), xb[2], gacc[j]);
      gacc[j] = ffma2(dup2(wb.w), xb[3], gacc[j]);
    }
  }
  u64 gate[J];
#pragma unroll
  for (int j = 0; j < J; ++j) {
    const float b = __ldg(&bg[g + G * j]);
    F2 t; t.u = gacc[j];
    F2 gt;
    gt.f.x = 1.f / (1.f + __expf(-(t.f.x + b)));
    gt.f.y = 1.f / (1.f + __expf(-(t.f.y + b)));
    gate[j] = gt.u;
  }
  u64 acc[J][3];
#pragma unroll
  for (int j = 0; j < J; ++j) { acc[j][0] = 0ull; acc[j][1] = 0ull; acc[j][2] = 0ull; }
#pragma unroll 1
  for (int h = 0; h < H; h += 8) {
    u64 xa[3][4], xb[3][4];
#pragma unroll
    for (int cc = 0; cc < 4; ++cc) {
      xa[0][cc] = ld2(&vh[0][h + cc][2 * p]);
      xa[1][cc] = ld2(&vh[1][h + cc][2 * p]);
      xa[2][cc] = ld2(&vh[2][h + cc][2 * p]);
    }
#pragma unroll
    for (int cc = 0; cc < 4; ++cc) {
      xb[0][cc] = ld2(&vh[0][h + 4 + cc][2 * p]);
      xb[1][cc] = ld2(&vh[1][h + 4 + cc][2 * p]);
      xb[2][cc] = ld2(&vh[2][h + 4 + cc][2 * p]);
    }
#pragma unroll
    for (int j = 0; j < J; ++j) {
      const int o = g + G * j;
      const float4 wa = __ldg(reinterpret_cast<const float4*>(Wvo + (size_t)o * H + h));
      const float4 wb = __ldg(reinterpret_cast<const float4*>(Wvo + (size_t)o * H + h + 4));
      const u64 a0 = dup2(wa.x), a1 = dup2(wa.y), a2 = dup2(wa.z), a3 = dup2(wa.w);
#pragma unroll
      for (int i = 0; i < 3; ++i) {
        acc[j][i] = ffma2(a0, xa[i][0], acc[j][i]);
        acc[j][i] = ffma2(a1, xa[i][1], acc[j][i]);
        acc[j][i] = ffma2(a2, xa[i][2], acc[j][i]);
        acc[j][i] = ffma2(a3, xa[i][3], acc[j][i]);
      }
      const u64 b0 = dup2(wb.x), b1 = dup2(wb.y), b2 = dup2(wb.z), b3 = dup2(wb.w);
#pragma unroll
      for (int i = 0; i < 3; ++i) {
        acc[j][i] = ffma2(b0, xb[i][0], acc[j][i]);
        acc[j][i] = ffma2(b1, xb[i][1], acc[j][i]);
        acc[j][i] = ffma2(b2, xb[i][2], acc[j][i]);
        acc[j][i] = ffma2(b3, xb[i][3], acc[j][i]);
      }
    }
  }
#pragma unroll
  for (int j = 0; j < J; ++j) {
    const int o = g + G * j;
    st2(&v[0][o][2 * p], fmul2(gate[j], acc[j][0]));
    st2(&v[1][o][2 * p], fmul2(gate[j], acc[j][1]));
    st2(&v[2][o][2 * p], fmul2(gate[j], acc[j][2]));
  }
}

template<int OUT, bool LEAKY>
__device__ __forceinline__ void scalar_act(float (*so)[R], float (*dst)[R], int g, int p)
{
  constexpr int J = OUT / G;
#pragma unroll
  for (int j = 0; j < J; ++j) {
    const int o = g + G * j;
    F2 t; t.u = ld2(&so[o][2 * p]);
    if (LEAKY) {
      t.f.x = t.f.x >= 0.f ? t.f.x : 0.01f * t.f.x;
      t.f.y = t.f.y >= 0.f ? t.f.y : 0.01f * t.f.y;
    }
    st2(&dst[o][2 * p], t.u);
  }
}

template<int OUT>
__device__ __forceinline__ void vnleaky_ew(float (*x)[256][R], float (*d)[256][R], int g, int p)
{
  constexpr int J = OUT / G;
#pragma unroll
  for (int j = 0; j < J; ++j) {
    const int o = g + G * j;
    F2 x0, x1, x2, d0, d1, d2;
    x0.u = ld2(&x[0][o][2 * p]); x1.u = ld2(&x[1][o][2 * p]); x2.u = ld2(&x[2][o][2 * p]);
    d0.u = ld2(&d[0][o][2 * p]); d1.u = ld2(&d[1][o][2 * p]); d2.u = ld2(&d[2][o][2 * p]);
    u64 dotu = fmul2(x0.u, d0.u); dotu = ffma2(x1.u, d1.u, dotu); dotu = ffma2(x2.u, d2.u, dotu);
    u64 dsqu = fmul2(d0.u, d0.u); dsqu = ffma2(d1.u, d1.u, dsqu); dsqu = ffma2(d2.u, d2.u, dsqu);
    F2 dot, dsq; dot.u = dotu; dsq.u = dsqu;
    F2 o0, o1, o2;
#pragma unroll
    for (int h = 0; h < 2; ++h) {
      const float dt = h ? dot.f.y : dot.f.x;
      const float ds = h ? dsq.f.y : dsq.f.x;
      const float xa = h ? x0.f.y : x0.f.x;
      const float xb = h ? x1.f.y : x1.f.x;
      const float xc = h ? x2.f.y : x2.f.x;
      const float da = h ? d0.f.y : d0.f.x;
      const float db = h ? d1.f.y : d1.f.x;
      const float dc = h ? d2.f.y : d2.f.x;
      const float t = dt / (ds + 1e-6f);
      const bool pos = (dt >= 0.f);
      const float na = pos ? xa : (xa - t * da);
      const float nb = pos ? xb : (xb - t * db);
      const float nc = pos ? xc : (xc - t * dc);
      const float ra = 0.2f * xa + 0.8f * na;
      const float rb = 0.2f * xb + 0.8f * nb;
      const float rc = 0.2f * xc + 0.8f * nc;
      if (h) { o0.f.y = ra; o1.f.y = rb; o2.f.y = rc; }
      else   { o0.f.x = ra; o1.f.x = rb; o2.f.x = rc; }
    }
    st2(&x[0][o][2 * p], o0.u);
    st2(&x[1][o][2 * p], o1.u);
    st2(&x[2][o][2 * p], o2.u);
  }
}

__global__ __launch_bounds__(NT, 1)
void pe_kernel(const float* __restrict__ h_sca, const float* __restrict__ h_vec,
               const float* __restrict__ pos_compose, const float* __restrict__ pos,
               const float* __restrict__ g1_Wvh, const float* __restrict__ g1_Ws,
               const float* __restrict__ g1_Wvo, const float* __restrict__ g1_Wg,
               const float* __restrict__ g1_bg,  const float* __restrict__ g1_Wd,
               const float* __restrict__ g2_Wvh, const float* __restrict__ g2_Ws,
               const float* __restrict__ g2_Wvo, const float* __restrict__ g2_Wg,
               const float* __restrict__ g2_bg,
               const float* __restrict__ a1_Wvh, const float* __restrict__ a1_Ws,
               const float* __restrict__ a1_Wvo, const float* __restrict__ a1_Wg,
               const float* __restrict__ a1_bg,  const float* __restrict__ a1_Wd,
               const float* __restrict__ a2_Wvh, const float* __restrict__ a2_Ws,
               const float* __restrict__ a2_Wvo, const float* __restrict__ a2_Wg,
               const float* __restrict__ a2_bg,  const float* __restrict__ a2_Wd,
               const float* __restrict__ f_Wvh,  const float* __restrict__ f_Ws,
               const int* __restrict__ idx_focal,
               float* __restrict__ out, int F)
{
  extern __shared__ char smraw[];
  SM& S = *reinterpret_cast<SM*>(smraw);
  const int tid = threadIdx.x;
  const int g = tid >> 3;    // channel group 0..31
  const int p = tid & 7;     // row pair     0..7
  const int row0 = blockIdx.x * R;

  if (tid < R) {
    const int row = row0 + tid;
    S.nidx[tid] = (row < F) ? idx_focal[row] : 0;
  }
  __syncthreads();

  if (tid < 3 * R) {
    const int rr = tid / 3, i = tid % 3;
    const int row = row0 + rr;
    const int n = S.nidx[rr];
    const float pv = (row < F) ? pos[(size_t)row * 3 + i] : 0.f;
    S.rp[i][rr] = pv - pos_compose[(size_t)n * 3 + i];
  }

  for (int rr = 0; rr < R; ++rr) {
    const size_t n = (size_t)S.nidx[rr];
    S.ssc[tid][rr] = __ldg(&h_sca[n * 256 + tid]);
    if (tid < 192) S.sv[tid % 3][tid / 3][rr] = __ldg(&h_vec[n * 192 + tid]);
  }
  __syncthreads();

  // ================= g1: gv_perceptron =================
  matvec_v<128, 64, true>(g1_Wvh, S.sv, S.sh, S.snorm, g, p);
  __syncthreads();
  matvec_s2<128, 128, 256>(g1_Ws, S.snorm, S.ssc, S.so, g, p);
  __syncthreads();
  gated_outv<128, 128, 128>(g1_Wvo, g1_Wg, g1_bg, S.sh, S.so, S.sv, g, p);
  scalar_act<128, true>(S.so, S.ssc, g, p);
  __syncthreads();
  matvec_v<128, 128, false>(g1_Wd, S.sv, S.sh, S.snorm, g, p);
  __syncthreads();
  vnleaky_ew<128>(S.sv, S.sh, g, p);
  __syncthreads();

  // ================= g2: gv_linear =================
  matvec_v<128, 128, true>(g2_Wvh, S.sv, S.sh, S.snorm, g, p);
  __syncthreads();
  matvec_s2<128, 128, 128>(g2_Ws, S.snorm, S.ssc, S.so, g, p);
  __syncthreads();
  gated_outv<128, 128, 128>(g2_Wvo, g2_Wg, g2_bg, S.sh, S.so, S.sv, g, p);
  scalar_act<128, false>(S.so, S.ssc, g, p);
  __syncthreads();

  // ================= a1: gv_perceptron =================
  matvec_v<256, 128, true>(a1_Wvh, S.sv, S.sh, S.snorm, g, p);
  __syncthreads();
  matvec_s2<128, 256, 128>(a1_Ws, S.snorm, S.ssc, S.so, g, p);
  __syncthreads();
  gated_outv<256, 256, 128>(a1_Wvo, a1_Wg, a1_bg, S.sh, S.so, S.sv, g, p);
  scalar_act<128, true>(S.so, S.ssc, g, p);
  __syncthreads();
  matvec_v<256, 256, false>(a1_Wd, S.sv, S.sh, S.snorm, g, p);
  __syncthreads();
  vnleaky_ew<256>(S.sv, S.sh, g, p);
  __syncthreads();

  // ===== split: inner = <x_vec2, relpos> -> ssc[128..255] =====
  {
    const u64 rp0 = ld2(&S.rp[0][2 * p]);
    const u64 rp1 = ld2(&S.rp[1][2 * p]);
    const u64 rp2 = ld2(&S.rp[2][2 * p]);
#pragma unroll
    for (int j = 0; j < 4; ++j) {
      const int o = g + G * j;
      u64 acc = fmul2(ld2(&S.sv[0][128 + o][2 * p]), rp0);
      acc = ffma2(ld2(&S.sv[1][128 + o][2 * p]), rp1, acc);
      acc = ffma2(ld2(&S.sv[2][128 + o][2 * p]), rp2, acc);
      st2(&S.ssc[128 + o][2 * p], acc);
    }
  }
  __syncthreads();

  // ================= a2: gv_perceptron (on x_vec = sv[0..127]) =================
  matvec_v<128, 128, true>(a2_Wvh, S.sv, S.sh, S.snorm, g, p);
  __syncthreads();
  matvec_s2<128, 128, 256>(a2_Ws, S.snorm, S.ssc, S.so, g, p);
  __syncthreads();
  gated_outv<128, 128, 128>(a2_Wvo, a2_Wg, a2_bg, S.sh, S.so, S.sv, g, p);
  scalar_act<128, true>(S.so, S.ssc, g, p);
  __syncthreads();
  matvec_v<128, 128, false>(a2_Wd, S.sv, S.sh, S.snorm, g, p);
  __syncthreads();
  vnleaky_ew<128>(S.sv, S.sh, g, p);
  __syncthreads();

  // ================= final: out = [||f_Wvh@v||, s3] @ f_Ws^T =================
  matvec_v<128, 128, true>(f_Wvh, S.sv, S.sh, S.snorm, g, p);
  __syncthreads();
  {
    u64 acc = 0ull;
#pragma unroll
    for (int kk = 0; kk < 8; ++kk) {
      const int k = g * 8 + kk;
      const u64 xv = (k < 128) ? ld2(&S.snorm[k][2 * p]) : ld2(&S.ssc[k - 128][2 * p]);
      acc = ffma2(dup2(__ldg(&f_Ws[k])), xv, acc);
    }
    st2(&S.so[g][2 * p], acc);
  }
  __syncthreads();
  if (tid < R) {
    const int row = row0 + tid;
    float acc = 0.f;
#pragma unroll
    for (int gg = 0; gg < G; ++gg) acc += S.so[gg][tid];
    if (row < F) out[row] = acc;
  }
}

extern "C" void kernel_launch(void* const* d_in, const int* in_sizes, int n_in,
                              void* d_out, int out_size)
{
  const float* h_sca       = (const float*)d_in[0];
  const float* h_vec       = (const float*)d_in[1];
  const float* pos_compose = (const float*)d_in[2];
  const float* pos         = (const float*)d_in[3];
  const float* g1_Wvh = (const float*)d_in[4];
  const float* g1_Ws  = (const float*)d_in[5];
  const float* g1_Wvo = (const float*)d_in[6];
  const float* g1_Wg  = (const float*)d_in[7];
  const float* g1_bg  = (const float*)d_in[8];
  const float* g1_Wd  = (const float*)d_in[9];
  const float* g2_Wvh = (const float*)d_in[10];
  const float* g2_Ws  = (const float*)d_in[11];
  const float* g2_Wvo = (const float*)d_in[12];
  const float* g2_Wg  = (const float*)d_in[13];
  const float* g2_bg  = (const float*)d_in[14];
  const float* a1_Wvh = (const float*)d_in[15];
  const float* a1_Ws  = (const float*)d_in[16];
  const float* a1_Wvo = (const float*)d_in[17];
  const float* a1_Wg  = (const float*)d_in[18];
  const float* a1_bg  = (const float*)d_in[19];
  const float* a1_Wd  = (const float*)d_in[20];
  const float* a2_Wvh = (const float*)d_in[21];
  const float* a2_Ws  = (const float*)d_in[22];
  const float* a2_Wvo = (const float*)d_in[23];
  const float* a2_Wg  = (const float*)d_in[24];
  const float* a2_bg  = (const float*)d_in[25];
  const float* a2_Wd  = (const float*)d_in[26];
  const float* f_Wvh  = (const float*)d_in[27];
  const float* f_Ws   = (const float*)d_in[28];
  const int*   idx_focal = (const int*)d_in[29];

  const int F = in_sizes[3] / 3;   // pos is (F, 3)
  const int grid = (F + R - 1) / R;

  cudaFuncSetAttribute(pe_kernel, cudaFuncAttributeMaxDynamicSharedMemorySize,
                       (int)sizeof(SM));

  pe_kernel<<<grid, NT, sizeof(SM)>>>(
      h_sca, h_vec, pos_compose, pos,
      g1_Wvh, g1_Ws, g1_Wvo, g1_Wg, g1_bg, g1_Wd,
      g2_Wvh, g2_Ws, g2_Wvo, g2_Wg, g2_bg,
      a1_Wvh, a1_Ws, a1_Wvo, a1_Wg, a1_bg, a1_Wd,
      a2_Wvh, a2_Ws, a2_Wvo, a2_Wg, a2_bg, a2_Wd,
      f_Wvh, f_Ws, idx_focal,
      (float*)d_out, F);
}

// round 11
// speedup vs baseline: 1.2178x; 1.1433x over previous
#include <cuda_runtime.h>
#include <math.h>

// ---------------------------------------------------------------------------
// PositionEvaluator, round 9: same benched envelope as R1/R3/R8
// (NT=256, R=16, occ=1, FFMA2 row pairs), plus software-pipelined weight
// prefetch: weights live in L2 (~250 cyc; L1D is thrashed by the 2.26MB
// weight chain vs ~88KB cache), so every reduction loop ping-pongs two
// register weight buffers — load chunk i+1, FMA chunk i — to keep the
// L2 latency covered by FMA work instead of exposed as long_scoreboard.
// Thread map: p = tid & 7 (row pair 0..7), g = tid >> 3 (group 0..31).
// ---------------------------------------------------------------------------

#define R  16
#define G  32
#define NT 256

typedef unsigned long long u64;
union F2 { u64 u; float2 f; };

__device__ __forceinline__ u64 ffma2(u64 a, u64 b, u64 c) {
  u64 d; asm("fma.rn.f32x2 %0, %1, %2, %3;" : "=l"(d) : "l"(a), "l"(b), "l"(c)); return d;
}
__device__ __forceinline__ u64 fmul2(u64 a, u64 b) {
  u64 d; asm("mul.rn.f32x2 %0, %1, %2;" : "=l"(d) : "l"(a), "l"(b)); return d;
}
__device__ __forceinline__ u64 dup2(float w) {
  u64 d; asm("mov.b64 %0, {%1, %1};" : "=l"(d) : "f"(w)); return d;
}
__device__ __forceinline__ u64 ld2(const float* p) {
  return *reinterpret_cast<const u64*>(p);
}
__device__ __forceinline__ void st2(float* p, u64 v) {
  *reinterpret_cast<u64*>(p) = v;
}

struct SM {
  float sv[3][256][R];
  float sh[3][256][R];
  float snorm[256][R];
  float ssc[256][R];
  float so[128][R];
  float rp[3][R];
  int   nidx[R];
};

// ---------------- vector dot with weight ping-pong ----------------
// acc[j][i] += sum_c W[g+G*j][c] * x[i][c][pair]
template<int J, int CIN>
__device__ __forceinline__ void vdot_all(const float* __restrict__ W,
                                         float (*x)[256][R],
                                         u64 (&acc)[J][3], int g, int p)
{
  constexpr int CH = (J >= 8) ? 4 : 8;   // chunk columns
  constexpr int NF = CH / 4;             // float4 per j per chunk
  static_assert(CIN % (2 * CH) == 0, "CIN must be multiple of 2*CH");
  float4 A[J][NF], B[J][NF];
#pragma unroll
  for (int j = 0; j < J; ++j)
#pragma unroll
    for (int q = 0; q < NF; ++q)
      A[j][q] = __ldg(reinterpret_cast<const float4*>(W + (size_t)(g + G * j) * CIN) + q);
#pragma unroll 1
  for (int c = 0; c < CIN; c += 2 * CH) {
    // prefetch chunk c+CH into B
#pragma unroll
    for (int j = 0; j < J; ++j)
#pragma unroll
      for (int q = 0; q < NF; ++q)
        B[j][q] = __ldg(reinterpret_cast<const float4*>(W + (size_t)(g + G * j) * CIN + c + CH) + q);
    // FMA chunk c with A
    {
      u64 xv[3][CH];
#pragma unroll
      for (int t = 0; t < CH; ++t) {
        xv[0][t] = ld2(&x[0][c + t][2 * p]);
        xv[1][t] = ld2(&x[1][c + t][2 * p]);
        xv[2][t] = ld2(&x[2][c + t][2 * p]);
      }
#pragma unroll
      for (int j = 0; j < J; ++j)
#pragma unroll
        for (int q = 0; q < NF; ++q) {
          const u64 w0 = dup2(A[j][q].x), w1 = dup2(A[j][q].y);
          const u64 w2 = dup2(A[j][q].z), w3 = dup2(A[j][q].w);
#pragma unroll
          for (int i = 0; i < 3; ++i) {
            acc[j][i] = ffma2(w0, xv[i][4 * q + 0], acc[j][i]);
            acc[j][i] = ffma2(w1, xv[i][4 * q + 1], acc[j][i]);
            acc[j][i] = ffma2(w2, xv[i][4 * q + 2], acc[j][i]);
            acc[j][i] = ffma2(w3, xv[i][4 * q + 3], acc[j][i]);
          }
        }
    }
    // prefetch chunk c+2CH (wrapped on last iter; value unused then) into A
    const int cn = (c + 2 * CH < CIN) ? (c + 2 * CH) : 0;
#pragma unroll
    for (int j = 0; j < J; ++j)
#pragma unroll
      for (int q = 0; q < NF; ++q)
        A[j][q] = __ldg(reinterpret_cast<const float4*>(W + (size_t)(g + G * j) * CIN + cn) + q);
    // FMA chunk c+CH with B
    {
      u64 xv[3][CH];
#pragma unroll
      for (int t = 0; t < CH; ++t) {
        xv[0][t] = ld2(&x[0][c + CH + t][2 * p]);
        xv[1][t] = ld2(&x[1][c + CH + t][2 * p]);
        xv[2][t] = ld2(&x[2][c + CH + t][2 * p]);
      }
#pragma unroll
      for (int j = 0; j < J; ++j)
#pragma unroll
        for (int q = 0; q < NF; ++q) {
          const u64 w0 = dup2(B[j][q].x), w1 = dup2(B[j][q].y);
          const u64 w2 = dup2(B[j][q].z), w3 = dup2(B[j][q].w);
#pragma unroll
          for (int i = 0; i < 3; ++i) {
            acc[j][i] = ffma2(w0, xv[i][4 * q + 0], acc[j][i]);
            acc[j][i] = ffma2(w1, xv[i][4 * q + 1], acc[j][i]);
            acc[j][i] = ffma2(w2, xv[i][4 * q + 2], acc[j][i]);
            acc[j][i] = ffma2(w3, xv[i][4 * q + 3], acc[j][i]);
          }
        }
    }
  }
}

// ---------------- scalar dot segment with weight ping-pong ----------------
// acc[j] += sum_{k<Kseg} W[g+G*j][OFF+k] * x[k][pair]   (row stride K)
template<int J, int K, int OFF, int Kseg>
__device__ __forceinline__ void sdot_seg(const float* __restrict__ W,
                                         float (*x)[R],
                                         u64 (&acc)[J], int g, int p)
{
  constexpr int CH = (J >= 8) ? 8 : 16;
  constexpr int NF = CH / 4;
  static_assert(Kseg % (2 * CH) == 0, "Kseg must be multiple of 2*CH");
  float4 A[J][NF], B[J][NF];
#pragma unroll
  for (int j = 0; j < J; ++j)
#pragma unroll
    for (int q = 0; q < NF; ++q)
      A[j][q] = __ldg(reinterpret_cast<const float4*>(W + (size_t)(g + G * j) * K + OFF) + q);
#pragma unroll 1
  for (int k = 0; k < Kseg; k += 2 * CH) {
#pragma unroll
    for (int j = 0; j < J; ++j)
#pragma unroll
      for (int q = 0; q < NF; ++q)
        B[j][q] = __ldg(reinterpret_cast<const float4*>(W + (size_t)(g + G * j) * K + OFF + k + CH) + q);
    {
      u64 xv[CH];
#pragma unroll
      for (int t = 0; t < CH; ++t) xv[t] = ld2(&x[k + t][2 * p]);
#pragma unroll
      for (int j = 0; j < J; ++j)
#pragma unroll
        for (int q = 0; q < NF; ++q) {
          acc[j] = ffma2(dup2(A[j][q].x), xv[4 * q + 0], acc[j]);
          acc[j] = ffma2(dup2(A[j][q].y), xv[4 * q + 1], acc[j]);
          acc[j] = ffma2(dup2(A[j][q].z), xv[4 * q + 2], acc[j]);
          acc[j] = ffma2(dup2(A[j][q].w), xv[4 * q + 3], acc[j]);
        }
    }
    const int kn = (k + 2 * CH < Kseg) ? (k + 2 * CH) : 0;
#pragma unroll
    for (int j = 0; j < J; ++j)
#pragma unroll
      for (int q = 0; q < NF; ++q)
        A[j][q] = __ldg(reinterpret_cast<const float4*>(W + (size_t)(g + G * j) * K + OFF + kn) + q);
    {
      u64 xv[CH];
#pragma unroll
      for (int t = 0; t < CH; ++t) xv[t] = ld2(&x[k + CH + t][2 * p]);
#pragma unroll
      for (int j = 0; j < J; ++j)
#pragma unroll
        for (int q = 0; q < NF; ++q) {
          acc[j] = ffma2(dup2(B[j][q].x), xv[4 * q + 0], acc[j]);
          acc[j] = ffma2(dup2(B[j][q].y), xv[4 * q + 1], acc[j]);
          acc[j] = ffma2(dup2(B[j][q].z), xv[4 * q + 2], acc[j]);
          acc[j] = ffma2(dup2(B[j][q].w), xv[4 * q + 3], acc[j]);
        }
    }
  }
}

// ---------------- stage building blocks ----------------

template<int OUT, int CIN, bool NORM>
__device__ __forceinline__ void matvec_v(const float* __restrict__ W,
                                         float (*x)[256][R],
                                         float (*y)[256][R],
                                         float (*nrm)[R],
                                         int g, int p)
{
  constexpr int J = OUT / G;
  u64 acc[J][3];
#pragma unroll
  for (int j = 0; j < J; ++j) { acc[j][0] = 0ull; acc[j][1] = 0ull; acc[j][2] = 0ull; }
  vdot_all<J, CIN>(W, x, acc, g, p);
#pragma unroll
  for (int j = 0; j < J; ++j) {
    const int o = g + G * j;
    st2(&y[0][o][2 * p], acc[j][0]);
    st2(&y[1][o][2 * p], acc[j][1]);
    st2(&y[2][o][2 * p], acc[j][2]);
    if (NORM) {
      u64 s = fmul2(acc[j][0], acc[j][0]);
      s = ffma2(acc[j][1], acc[j][1], s);
      s = ffma2(acc[j][2], acc[j][2], s);
      F2 t; t.u = s;
      F2 n; n.f.x = sqrtf(t.f.x); n.f.y = sqrtf(t.f.y);
      st2(&nrm[o][2 * p], n.u);
    }
  }
}

template<int OUT, int K1, int K2>
__device__ __forceinline__ void matvec_s2(const float* __restrict__ W,
                                          float (*x1)[R], float (*x2)[R],
                                          float (*y)[R], int g, int p)
{
  constexpr int J = OUT / G;
  u64 acc[J];
#pragma unroll
  for (int j = 0; j < J; ++j) acc[j] = 0ull;
  sdot_seg<J, K1 + K2, 0,  K1>(W, x1, acc, g, p);
  sdot_seg<J, K1 + K2, K1, K2>(W, x2, acc, g, p);
#pragma unroll
  for (int j = 0; j < J; ++j) st2(&y[g + G * j][2 * p], acc[j]);
}

template<int OUT, int H, int KG>
__device__ __forceinline__ void gated_outv(const float* __restrict__ Wvo,
                                           const float* __restrict__ Wg,
                                           const float* __restrict__ bg,
                                           float (*vh)[256][R],
                                           float (*so)[R],
                                           float (*v)[256][R],
                                           int g, int p)
{
  constexpr int J = OUT / G;
  u64 gacc[J];
#pragma unroll
  for (int j = 0; j < J; ++j) gacc[j] = 0ull;
  sdot_seg<J, KG, 0, KG>(Wg, so, gacc, g, p);
  u64 gate[J];
#pragma unroll
  for (int j = 0; j < J; ++j) {
    const float b = __ldg(&bg[g + G * j]);
    F2 t; t.u = gacc[j];
    F2 gt;
    gt.f.x = 1.f / (1.f + __expf(-(t.f.x + b)));
    gt.f.y = 1.f / (1.f + __expf(-(t.f.y + b)));
    gate[j] = gt.u;
  }
  u64 acc[J][3];
#pragma unroll
  for (int j = 0; j < J; ++j) { acc[j][0] = 0ull; acc[j][1] = 0ull; acc[j][2] = 0ull; }
  vdot_all<J, H>(Wvo, vh, acc, g, p);
#pragma unroll
  for (int j = 0; j < J; ++j) {
    const int o = g + G * j;
    st2(&v[0][o][2 * p], fmul2(gate[j], acc[j][0]));
    st2(&v[1][o][2 * p], fmul2(gate[j], acc[j][1]));
    st2(&v[2][o][2 * p], fmul2(gate[j], acc[j][2]));
  }
}

template<int OUT, bool LEAKY>
__device__ __forceinline__ void scalar_act(float (*so)[R], float (*dst)[R], int g, int p)
{
  constexpr int J = OUT / G;
#pragma unroll
  for (int j = 0; j < J; ++j) {
    const int o = g + G * j;
    F2 t; t.u = ld2(&so[o][2 * p]);
    if (LEAKY) {
      t.f.x = t.f.x >= 0.f ? t.f.x : 0.01f * t.f.x;
      t.f.y = t.f.y >= 0.f ? t.f.y : 0.01f * t.f.y;
    }
    st2(&dst[o][2 * p], t.u);
  }
}

template<int OUT>
__device__ __forceinline__ void vnleaky_ew(float (*x)[256][R], float (*d)[256][R], int g, int p)
{
  constexpr int J = OUT / G;
#pragma unroll
  for (int j = 0; j < J; ++j) {
    const int o = g + G * j;
    F2 x0, x1, x2, d0, d1, d2;
    x0.u = ld2(&x[0][o][2 * p]); x1.u = ld2(&x[1][o][2 * p]); x2.u = ld2(&x[2][o][2 * p]);
    d0.u = ld2(&d[0][o][2 * p]); d1.u = ld2(&d[1][o][2 * p]); d2.u = ld2(&d[2][o][2 * p]);
    u64 dotu = fmul2(x0.u, d0.u); dotu = ffma2(x1.u, d1.u, dotu); dotu = ffma2(x2.u, d2.u, dotu);
    u64 dsqu = fmul2(d0.u, d0.u); dsqu = ffma2(d1.u, d1.u, dsqu); dsqu = ffma2(d2.u, d2.u, dsqu);
    F2 dot, dsq; dot.u = dotu; dsq.u = dsqu;
    F2 o0, o1, o2;
#pragma unroll
    for (int h = 0; h < 2; ++h) {
      const float dt = h ? dot.f.y : dot.f.x;
      const float ds = h ? dsq.f.y : dsq.f.x;
      const float xa = h ? x0.f.y : x0.f.x;
      const float xb = h ? x1.f.y : x1.f.x;
      const float xc = h ? x2.f.y : x2.f.x;
      const float da = h ? d0.f.y : d0.f.x;
      const float db = h ? d1.f.y : d1.f.x;
      const float dc = h ? d2.f.y : d2.f.x;
      const float t = dt / (ds + 1e-6f);
      const bool pos = (dt >= 0.f);
      const float na = pos ? xa : (xa - t * da);
      const float nb = pos ? xb : (xb - t * db);
      const float nc = pos ? xc : (xc - t * dc);
      const float ra = 0.2f * xa + 0.8f * na;
      const float rb = 0.2f * xb + 0.8f * nb;
      const float rc = 0.2f * xc + 0.8f * nc;
      if (h) { o0.f.y = ra; o1.f.y = rb; o2.f.y = rc; }
      else   { o0.f.x = ra; o1.f.x = rb; o2.f.x = rc; }
    }
    st2(&x[0][o][2 * p], o0.u);
    st2(&x[1][o][2 * p], o1.u);
    st2(&x[2][o][2 * p], o2.u);
  }
}

__global__ __launch_bounds__(NT, 1)
void pe_kernel(const float* __restrict__ h_sca, const float* __restrict__ h_vec,
               const float* __restrict__ pos_compose, const float* __restrict__ pos,
               const float* __restrict__ g1_Wvh, const float* __restrict__ g1_Ws,
               const float* __restrict__ g1_Wvo, const float* __restrict__ g1_Wg,
               const float* __restrict__ g1_bg,  const float* __restrict__ g1_Wd,
               const float* __restrict__ g2_Wvh, const float* __restrict__ g2_Ws,
               const float* __restrict__ g2_Wvo, const float* __restrict__ g2_Wg,
               const float* __restrict__ g2_bg,
               const float* __restrict__ a1_Wvh, const float* __restrict__ a1_Ws,
               const float* __restrict__ a1_Wvo, const float* __restrict__ a1_Wg,
               const float* __restrict__ a1_bg,  const float* __restrict__ a1_Wd,
               const float* __restrict__ a2_Wvh, const float* __restrict__ a2_Ws,
               const float* __restrict__ a2_Wvo, const float* __restrict__ a2_Wg,
               const float* __restrict__ a2_bg,  const float* __restrict__ a2_Wd,
               const float* __restrict__ f_Wvh,  const float* __restrict__ f_Ws,
               const int* __restrict__ idx_focal,
               float* __restrict__ out, int F)
{
  extern __shared__ char smraw[];
  SM& S = *reinterpret_cast<SM*>(smraw);
  const int tid = threadIdx.x;
  const int g = tid >> 3;    // channel group 0..31
  const int p = tid & 7;     // row pair     0..7
  const int row0 = blockIdx.x * R;

  if (tid < R) {
    const int row = row0 + tid;
    S.nidx[tid] = (row < F) ? idx_focal[row] : 0;
  }
  __syncthreads();

  if (tid < 3 * R) {
    const int rr = tid / 3, i = tid % 3;
    const int row = row0 + rr;
    const int n = S.nidx[rr];
    const float pv = (row < F) ? pos[(size_t)row * 3 + i] : 0.f;
    S.rp[i][rr] = pv - pos_compose[(size_t)n * 3 + i];
  }

  for (int rr = 0; rr < R; ++rr) {
    const size_t n = (size_t)S.nidx[rr];
    S.ssc[tid][rr] = __ldg(&h_sca[n * 256 + tid]);
    if (tid < 192) S.sv[tid % 3][tid / 3][rr] = __ldg(&h_vec[n * 192 + tid]);
  }
  __syncthreads();

  // ================= g1: gv_perceptron =================
  matvec_v<128, 64, true>(g1_Wvh, S.sv, S.sh, S.snorm, g, p);
  __syncthreads();
  matvec_s2<128, 128, 256>(g1_Ws, S.snorm, S.ssc, S.so, g, p);
  __syncthreads();
  gated_outv<128, 128, 128>(g1_Wvo, g1_Wg, g1_bg, S.sh, S.so, S.sv, g, p);
  scalar_act<128, true>(S.so, S.ssc, g, p);
  __syncthreads();
  matvec_v<128, 128, false>(g1_Wd, S.sv, S.sh, S.snorm, g, p);
  __syncthreads();
  vnleaky_ew<128>(S.sv, S.sh, g, p);
  __syncthreads();

  // ================= g2: gv_linear =================
  matvec_v<128, 128, true>(g2_Wvh, S.sv, S.sh, S.snorm, g, p);
  __syncthreads();
  matvec_s2<128, 128, 128>(g2_Ws, S.snorm, S.ssc, S.so, g, p);
  __syncthreads();
  gated_outv<128, 128, 128>(g2_Wvo, g2_Wg, g2_bg, S.sh, S.so, S.sv, g, p);
  scalar_act<128, false>(S.so, S.ssc, g, p);
  __syncthreads();

  // ================= a1: gv_perceptron =================
  matvec_v<256, 128, true>(a1_Wvh, S.sv, S.sh, S.snorm, g, p);
  __syncthreads();
  matvec_s2<128, 256, 128>(a1_Ws, S.snorm, S.ssc, S.so, g, p);
  __syncthreads();
  gated_outv<256, 256, 128>(a1_Wvo, a1_Wg, a1_bg, S.sh, S.so, S.sv, g, p);
  scalar_act<128, true>(S.so, S.ssc, g, p);
  __syncthreads();
  matvec_v<256, 256, false>(a1_Wd, S.sv, S.sh, S.snorm, g, p);
  __syncthreads();
  vnleaky_ew<256>(S.sv, S.sh, g, p);
  __syncthreads();

  // ===== split: inner = <x_vec2, relpos> -> ssc[128..255] =====
  {
    const u64 rp0 = ld2(&S.rp[0][2 * p]);
    const u64 rp1 = ld2(&S.rp[1][2 * p]);
    const u64 rp2 = ld2(&S.rp[2][2 * p]);
#pragma unroll
    for (int j = 0; j < 4; ++j) {
      const int o = g + G * j;
      u64 acc = fmul2(ld2(&S.sv[0][128 + o][2 * p]), rp0);
      acc = ffma2(ld2(&S.sv[1][128 + o][2 * p]), rp1, acc);
      acc = ffma2(ld2(&S.sv[2][128 + o][2 * p]), rp2, acc);
      st2(&S.ssc[128 + o][2 * p], acc);
    }
  }
  __syncthreads();

  // ================= a2: gv_perceptron =================
  matvec_v<128, 128, true>(a2_Wvh, S.sv, S.sh, S.snorm, g, p);
  __syncthreads();
  matvec_s2<128, 128, 256>(a2_Ws, S.snorm, S.ssc, S.so, g, p);
  __syncthreads();
  gated_outv<128, 128, 128>(a2_Wvo, a2_Wg, a2_bg, S.sh, S.so, S.sv, g, p);
  scalar_act<128, true>(S.so, S.ssc, g, p);
  __syncthreads();
  matvec_v<128, 128, false>(a2_Wd, S.sv, S.sh, S.snorm, g, p);
  __syncthreads();
  vnleaky_ew<128>(S.sv, S.sh, g, p);
  __syncthreads();

  // ================= final =================
  matvec_v<128, 128, true>(f_Wvh, S.sv, S.sh, S.snorm, g, p);
  __syncthreads();
  {
    u64 acc = 0ull;
#pragma unroll
    for (int kk = 0; kk < 8; ++kk) {
      const int k = g * 8 + kk;
      const u64 xv = (k < 128) ? ld2(&S.snorm[k][2 * p]) : ld2(&S.ssc[k - 128][2 * p]);
      acc = ffma2(dup2(__ldg(&f_Ws[k])), xv, acc);
    }
    st2(&S.so[g][2 * p], acc);
  }
  __syncthreads();
  if (tid < R) {
    const int row = row0 + tid;
    float acc = 0.f;
#pragma unroll
    for (int gg = 0; gg < G; ++gg) acc += S.so[gg][tid];
    if (row < F) out[row] = acc;
  }
}

extern "C" void kernel_launch(void* const* d_in, const int* in_sizes, int n_in,
                              void* d_out, int out_size)
{
  const float* h_sca       = (const float*)d_in[0];
  const float* h_vec       = (const float*)d_in[1];
  const float* pos_compose = (const float*)d_in[2];
  const float* pos         = (const float*)d_in[3];
  const float* g1_Wvh = (const float*)d_in[4];
  const float* g1_Ws  = (const float*)d_in[5];
  const float* g1_Wvo = (const float*)d_in[6];
  const float* g1_Wg  = (const float*)d_in[7];
  const float* g1_bg  = (const float*)d_in[8];
  const float* g1_Wd  = (const float*)d_in[9];
  const float* g2_Wvh = (const float*)d_in[10];
  const float* g2_Ws  = (const float*)d_in[11];
  const float* g2_Wvo = (const float*)d_in[12];
  const float* g2_Wg  = (const float*)d_in[13];
  const float* g2_bg  = (const float*)d_in[14];
  const float* a1_Wvh = (const float*)d_in[15];
  const float* a1_Ws  = (const float*)d_in[16];
  const float* a1_Wvo = (const float*)d_in[17];
  const float* a1_Wg  = (const float*)d_in[18];
  const float* a1_bg  = (const float*)d_in[19];
  const float* a1_Wd  = (const float*)d_in[20];
  const float* a2_Wvh = (const float*)d_in[21];
  const float* a2_Ws  = (const float*)d_in[22];
  const float* a2_Wvo = (const float*)d_in[23];
  const float* a2_Wg  = (const float*)d_in[24];
  const float* a2_bg  = (const float*)d_in[25];
  const float* a2_Wd  = (const float*)d_in[26];
  const float* f_Wvh  = (const float*)d_in[27];
  const float* f_Ws   = (const float*)d_in[28];
  const int*   idx_focal = (const int*)d_in[29];

  const int F = in_sizes[3] / 3;   // pos is (F, 3)
  const int grid = (F + R - 1) / R;

  cudaFuncSetAttribute(pe_kernel, cudaFuncAttributeMaxDynamicSharedMemorySize,
                       (int)sizeof(SM));

  pe_kernel<<<grid, NT, sizeof(SM)>>>(
      h_sca, h_vec, pos_compose, pos,
      g1_Wvh, g1_Ws, g1_Wvo, g1_Wg, g1_bg, g1_Wd,
      g2_Wvh, g2_Ws, g2_Wvo, g2_Wg, g2_bg,
      a1_Wvh, a1_Ws, a1_Wvo, a1_Wg, a1_bg, a1_Wd,
      a2_Wvh, a2_Ws, a2_Wvo, a2_Wg, a2_bg, a2_Wd,
      f_Wvh, f_Ws, idx_focal,
      (float*)d_out, F);
}